// round 17
// baseline (speedup 1.0000x reference)
#include <cuda_runtime.h>
#include <cuda_fp16.h>
#include <cstdint>

#define HD 128
#define NMAX 100000
#define EMAX 1600000
#define SCAN_B 1024
#define LDW 136   // padded smem row stride in halves (272 B: conflict-free ldmatrix)

// -------- scratch (device globals; no allocations allowed) --------
__device__ float  g_deg[NMAX];
__device__ float  g_dinv[NMAX];
__device__ __half g_Ah[(size_t)NMAX * HD];   // GEMM outputs (gather source)
__device__ __half g_Bh[(size_t)NMAX * HD];   // x-fp16 / agg outputs (GEMM + classifier input)
__device__ __half g_Wh[3 * 128 * 128];       // pre-converted fp16 weights
__device__ float  g_as[NMAX];
__device__ float  g_ad[NMAX];
__device__ int    g_cnt[NMAX];
__device__ int    g_rowptr[NMAX + 1];
__device__ int    g_cur[NMAX + 1];
__device__ int    g_bsum[128];
__device__ int    g_csr_src[EMAX];
__device__ float  g_csr_coef[EMAX];

__device__ __forceinline__ float leaky(float x) { return x > 0.f ? x : 0.2f * x; }

__device__ __forceinline__ unsigned sptr(const void* p) {
    return (unsigned)__cvta_generic_to_shared(p);
}

__device__ __forceinline__ void ldsm_x4(unsigned& r0, unsigned& r1, unsigned& r2, unsigned& r3,
                                        unsigned addr) {
    asm volatile("ldmatrix.sync.aligned.m8n8.x4.shared.b16 {%0,%1,%2,%3}, [%4];"
                 : "=r"(r0), "=r"(r1), "=r"(r2), "=r"(r3) : "r"(addr));
}

__device__ __forceinline__ void ldsm_x4_t(unsigned& r0, unsigned& r1, unsigned& r2, unsigned& r3,
                                          unsigned addr) {
    asm volatile("ldmatrix.sync.aligned.m8n8.x4.trans.shared.b16 {%0,%1,%2,%3}, [%4];"
                 : "=r"(r0), "=r"(r1), "=r"(r2), "=r"(r3) : "r"(addr));
}

__device__ __forceinline__ void mma16816(float& c0, float& c1, float& c2, float& c3,
                                         unsigned a0, unsigned a1, unsigned a2, unsigned a3,
                                         unsigned b0, unsigned b1) {
    asm volatile("mma.sync.aligned.m16n8k16.row.col.f32.f16.f16.f32 "
                 "{%0,%1,%2,%3}, {%4,%5,%6,%7}, {%8,%9}, {%0,%1,%2,%3};"
                 : "+f"(c0), "+f"(c1), "+f"(c2), "+f"(c3)
                 : "r"(a0), "r"(a1), "r"(a2), "r"(a3), "r"(b0), "r"(b1));
}

__device__ __forceinline__ unsigned packh2(float a, float b) {
    __half2 h = __floats2half2_rn(a, b);
    return *(unsigned*)&h;
}

__device__ __forceinline__ void cpa16(unsigned dst, const void* src, int szbytes) {
    asm volatile("cp.async.cg.shared.global [%0], [%1], 16, %2;"
                 :: "r"(dst), "l"(src), "r"(szbytes));
}

// unpack uint4 (8 fp16) and fma into 8-float accumulator
__device__ __forceinline__ void fma8(float* acc, uint4 q, float c) {
    __half2 h0 = *(__half2*)&q.x;
    __half2 h1 = *(__half2*)&q.y;
    __half2 h2 = *(__half2*)&q.z;
    __half2 h3 = *(__half2*)&q.w;
    float2 f0 = __half22float2(h0);
    float2 f1 = __half22float2(h1);
    float2 f2 = __half22float2(h2);
    float2 f3 = __half22float2(h3);
    acc[0] = fmaf(c, f0.x, acc[0]); acc[1] = fmaf(c, f0.y, acc[1]);
    acc[2] = fmaf(c, f1.x, acc[2]); acc[3] = fmaf(c, f1.y, acc[3]);
    acc[4] = fmaf(c, f2.x, acc[4]); acc[5] = fmaf(c, f2.y, acc[5]);
    acc[6] = fmaf(c, f3.x, acc[6]); acc[7] = fmaf(c, f3.y, acc[7]);
}

// ========= prep (chain A): x -> fp16 (into g_Bh), W1/W2/Wg -> fp16 =========
__global__ void k_prep(const float* __restrict__ x, const float* __restrict__ W1,
                       const float* __restrict__ W2, const float* __restrict__ Wg, int n) {
    int idx = blockIdx.x * blockDim.x + threadIdx.x;
    if (idx < n * 32) {
        int node = idx >> 5;
        int c4 = idx & 31;
        float4 a = *(const float4*)(x + (size_t)node * HD + c4 * 4);
        uint2 u;
        u.x = packh2(a.x, a.y);
        u.y = packh2(a.z, a.w);
        *(uint2*)(g_Bh + (size_t)node * HD + c4 * 4) = u;
    }
    if (idx < 3 * 2048) {
        int layer = idx / 2048;
        int off = (idx % 2048) * 8;
        const float* W = (layer == 0) ? W1 : ((layer == 1) ? W2 : Wg);
        float4 a = *(const float4*)(W + off);
        float4 b = *(const float4*)(W + off + 4);
        uint4 q;
        q.x = packh2(a.x, a.y);
        q.y = packh2(a.z, a.w);
        q.z = packh2(b.x, b.y);
        q.w = packh2(b.z, b.w);
        *(uint4*)(g_Wh + layer * 16384 + off) = q;
    }
}

// ================= CSR build (chain B) =================
__global__ void k_zero(int n) {
    int i = blockIdx.x * blockDim.x + threadIdx.x;
    if (i < n) { g_cnt[i] = 0; g_deg[i] = 1.0f; }
    if (i == 0) { g_rowptr[0] = 0; g_cur[0] = 0; }
}

__global__ void k_count_deg(const int* __restrict__ dst, const float* __restrict__ ew, int e) {
    int i = blockIdx.x * blockDim.x + threadIdx.x;
    if (i >= e) return;
    int d = dst[i];
    atomicAdd(&g_cnt[d], 1);
    atomicAdd(&g_deg[d], ew[i]);
}

__global__ __launch_bounds__(SCAN_B) void k_scan1(int n) {
    __shared__ int s[SCAN_B];
    int t = threadIdx.x;
    int g = blockIdx.x * SCAN_B + t;
    int v = (g < n) ? g_cnt[g] : 0;
    s[t] = v;
    __syncthreads();
    for (int o = 1; o < SCAN_B; o <<= 1) {
        int x = (t >= o) ? s[t - o] : 0;
        __syncthreads();
        s[t] += x;
        __syncthreads();
    }
    if (g < n) g_rowptr[g + 1] = s[t];
    if (t == SCAN_B - 1) g_bsum[blockIdx.x] = s[t];
}

__global__ __launch_bounds__(256) void k_scan3_dinv(int n, int nb) {
    __shared__ int s[128];
    int t = threadIdx.x;
    int v = 0;
    if (t < 128) { v = (t < nb) ? g_bsum[t] : 0; s[t] = v; }
    __syncthreads();
    for (int o = 1; o < 128; o <<= 1) {
        int x = (t >= o && t < 128) ? s[t - o] : 0;
        __syncthreads();
        if (t < 128) s[t] += x;
        __syncthreads();
    }
    if (t < 128) s[t] -= v;
    __syncthreads();
    int i = blockIdx.x * blockDim.x + t;
    if (i >= n) return;
    int val = g_rowptr[i + 1] + s[i >> 10];
    g_rowptr[i + 1] = val;
    g_cur[i + 1] = val;
    float d = g_deg[i];
    g_dinv[i] = d > 0.f ? rsqrtf(d) : 0.f;
}

__global__ void k_fill(const int* __restrict__ src, const int* __restrict__ dst,
                       const float* __restrict__ ew, int e) {
    int i = blockIdx.x * blockDim.x + threadIdx.x;
    if (i >= e) return;
    int s = src[i], d = dst[i];
    int pos = atomicAdd(&g_cur[d], 1);
    g_csr_src[pos] = s;
    g_csr_coef[pos] = g_dinv[s] * ew[i] * g_dinv[d];
}

// ======= persistent tensor-core GEMM, 512 threads (16 warps) =======
template<bool DOTS>
__global__ __launch_bounds__(512, 2) void k_gemm_tc(const __half* __restrict__ X,
                                                    const __half* __restrict__ Wh,
                                                    __half* __restrict__ Y,
                                                    const float* __restrict__ asrc,
                                                    const float* __restrict__ adst,
                                                    int n, int tot_tiles) {
    extern __shared__ __half smbuf[];
    __half* wt  = smbuf;
    __half* xb0 = smbuf + 128 * LDW;
    __half* xb1 = smbuf + 2 * 128 * LDW;
    __shared__ float sdots[256];
    const int t = threadIdx.x;
    const int bid = blockIdx.x;
    const int grid = gridDim.x;

    int myt = (bid < tot_tiles) ? ((tot_tiles - 1 - bid) / grid + 1) : 0;

    for (int i = t; i < 2048; i += 512) {
        int k = i >> 4;
        int c8 = i & 15;
        cpa16(sptr(wt + k * LDW + c8 * 8), Wh + k * 128 + c8 * 8, 16);
    }
    if (myt > 0) {
        int row0 = bid * 128;
        for (int i = t; i < 2048; i += 512) {
            int r = i >> 4;
            int c8 = i & 15;
            int gr = row0 + r;
            int grc = min(gr, n - 1);
            cpa16(sptr(xb0 + r * LDW + c8 * 8), X + (size_t)grc * HD + c8 * 8, (gr < n) ? 16 : 0);
        }
    }
    asm volatile("cp.async.commit_group;" ::: "memory");
    if (myt == 0) {
        asm volatile("cp.async.wait_group 0;" ::: "memory");
        return;
    }

    const int warp = t >> 5;
    const int lane = t & 31;
    const int rs = warp >> 1;
    const int ch = warp & 1;
    const int mrow = rs * 16;
    const int lrow = (lane & 7) + ((lane >> 3) & 1) * 8;
    const int lcol = (lane >> 4) * 8;
    const unsigned b_addr = sptr(wt + lrow * LDW + ch * 64 + lcol);
    const int rl = mrow + (lane >> 2);
    const int cb = (lane & 3) * 2;

    int tile = bid;
    for (int it = 0; it < myt; it++, tile += grid) {
        if (it + 1 < myt) {
            int row0n = (tile + grid) * 128;
            __half* dstb = ((it + 1) & 1) ? xb1 : xb0;
            for (int i = t; i < 2048; i += 512) {
                int r = i >> 4;
                int c8 = i & 15;
                int gr = row0n + r;
                int grc = min(gr, n - 1);
                cpa16(sptr(dstb + r * LDW + c8 * 8), X + (size_t)grc * HD + c8 * 8,
                      (gr < n) ? 16 : 0);
            }
            asm volatile("cp.async.commit_group;" ::: "memory");
            asm volatile("cp.async.wait_group 1;" ::: "memory");
        } else {
            asm volatile("cp.async.wait_group 0;" ::: "memory");
        }
        if (DOTS && t < 256) sdots[t] = 0.f;
        __syncthreads();

        const __half* xs = (it & 1) ? xb1 : xb0;
        const int row0 = tile * 128;
        const unsigned a_addr = sptr(xs + (mrow + lrow) * LDW + lcol);

        float acc[8][4];
        #pragma unroll
        for (int f = 0; f < 8; f++) {
            acc[f][0] = 0.f; acc[f][1] = 0.f; acc[f][2] = 0.f; acc[f][3] = 0.f;
        }

        #pragma unroll
        for (int ks = 0; ks < 8; ks++) {
            unsigned a0, a1, a2, a3;
            ldsm_x4(a0, a1, a2, a3, a_addr + ks * 32);
            unsigned bkrow = b_addr + (unsigned)(ks * 16 * LDW * 2);
            #pragma unroll
            for (int np = 0; np < 4; np++) {
                unsigned b0, b1, b2, b3;
                ldsm_x4_t(b0, b1, b2, b3, bkrow + np * 32);
                mma16816(acc[np * 2][0], acc[np * 2][1], acc[np * 2][2], acc[np * 2][3],
                         a0, a1, a2, a3, b0, b1);
                mma16816(acc[np * 2 + 1][0], acc[np * 2 + 1][1], acc[np * 2 + 1][2],
                         acc[np * 2 + 1][3], a0, a1, a2, a3, b2, b3);
            }
        }

        if (DOTS) {
            float ps1 = 0.f, pd1 = 0.f, ps2 = 0.f, pd2 = 0.f;
            #pragma unroll
            for (int f = 0; f < 8; f++) {
                int col = ch * 64 + f * 8 + cb;
                float s0 = __ldg(asrc + col);
                float s1 = __ldg(asrc + col + 1);
                float d0 = __ldg(adst + col);
                float d1 = __ldg(adst + col + 1);
                ps1 += acc[f][0] * s0 + acc[f][1] * s1;
                pd1 += acc[f][0] * d0 + acc[f][1] * d1;
                ps2 += acc[f][2] * s0 + acc[f][3] * s1;
                pd2 += acc[f][2] * d0 + acc[f][3] * d1;
            }
            for (int o = 1; o <= 2; o <<= 1) {
                ps1 += __shfl_xor_sync(0xffffffffu, ps1, o);
                pd1 += __shfl_xor_sync(0xffffffffu, pd1, o);
                ps2 += __shfl_xor_sync(0xffffffffu, ps2, o);
                pd2 += __shfl_xor_sync(0xffffffffu, pd2, o);
            }
            if ((lane & 3) == 0) {
                atomicAdd(&sdots[2 * rl], ps1);
                atomicAdd(&sdots[2 * rl + 1], pd1);
                atomicAdd(&sdots[2 * (rl + 8)], ps2);
                atomicAdd(&sdots[2 * (rl + 8) + 1], pd2);
            }
        }

        #pragma unroll
        for (int f = 0; f < 8; f++) {
            int col = ch * 64 + f * 8 + cb;
            int gr = row0 + rl;
            if (gr < n) {
                unsigned h = packh2(acc[f][0], acc[f][1]);
                *(unsigned*)(Y + (size_t)gr * HD + col) = h;
            }
            int gr2 = gr + 8;
            if (gr2 < n) {
                unsigned h = packh2(acc[f][2], acc[f][3]);
                *(unsigned*)(Y + (size_t)gr2 * HD + col) = h;
            }
        }

        if (DOTS) {
            __syncthreads();
            if (t < 128) {
                int gr = row0 + t;
                if (gr < n) {
                    g_as[gr] = sdots[2 * t];
                    g_ad[gr] = sdots[2 * t + 1];
                }
            }
        }
        __syncthreads();
    }
}

// ====== GCN aggregation: warp/node, half-warp row loads (uint4 = 8 fp16/lane) ======
// lanes 0-15 (half 0) process even rows of each pass; lanes 16-31 odd rows.
__global__ __launch_bounds__(256) void k_gcn_agg(const float* __restrict__ bias, int n) {
    int w = (blockIdx.x * blockDim.x + threadIdx.x) >> 5;
    if (w >= n) return;
    const int lane = threadIdx.x & 31;
    const int half = lane >> 4;
    const int hl = lane & 15;
    const int beg = g_rowptr[w];
    const int end = g_rowptr[w + 1];

    float acc[8];
    if (half == 0) {
        float di = g_dinv[w];
        float cself = di * di;
        #pragma unroll
        for (int i = 0; i < 8; i++) acc[i] = bias[hl * 8 + i];
        uint4 qa = *(const uint4*)(g_Ah + (size_t)w * HD + hl * 8);
        fma8(acc, qa, cself);
    } else {
        #pragma unroll
        for (int i = 0; i < 8; i++) acc[i] = 0.f;
    }

    for (int j0 = beg; j0 < end; j0 += 32) {
        int idx = j0 + lane;
        int s = 0;
        float c = 0.f;
        if (idx < end) { s = g_csr_src[idx]; c = g_csr_coef[idx]; }
        int m = min(32, end - j0);
        for (int j = 0; j < m; j += 4) {
            int   sA = __shfl_sync(0xffffffffu, s, j + half);
            float cA = __shfl_sync(0xffffffffu, c, j + half);
            int   sB = __shfl_sync(0xffffffffu, s, (j + 2 + half) & 31);
            float cB = __shfl_sync(0xffffffffu, c, (j + 2 + half) & 31);
            if (j + half >= m) cA = 0.f;
            if (j + 2 + half >= m) cB = 0.f;
            uint4 qA = *(const uint4*)(g_Ah + (size_t)sA * HD + hl * 8);
            uint4 qB = *(const uint4*)(g_Ah + (size_t)sB * HD + hl * 8);
            fma8(acc, qA, cA);
            fma8(acc, qB, cB);
        }
    }

    #pragma unroll
    for (int i = 0; i < 8; i++)
        acc[i] += __shfl_xor_sync(0xffffffffu, acc[i], 16);

    if (half == 0) {
        uint4 q;
        q.x = packh2(fmaxf(acc[0], 0.f), fmaxf(acc[1], 0.f));
        q.y = packh2(fmaxf(acc[2], 0.f), fmaxf(acc[3], 0.f));
        q.z = packh2(fmaxf(acc[4], 0.f), fmaxf(acc[5], 0.f));
        q.w = packh2(fmaxf(acc[6], 0.f), fmaxf(acc[7], 0.f));
        *(uint4*)(g_Bh + (size_t)w * HD + hl * 8) = q;
    }
}

// ====== GAT: fused softmax + aggregation, half-warp row loads ======
__global__ __launch_bounds__(256) void k_gat_agg(const float* __restrict__ bg, int n) {
    int w = (blockIdx.x * blockDim.x + threadIdx.x) >> 5;
    if (w >= n) return;
    const int lane = threadIdx.x & 31;
    const int half = lane >> 4;
    const int hl = lane & 15;
    const int beg = g_rowptr[w];
    const int end = g_rowptr[w + 1];

    float ad_d = g_ad[w];
    float a_self = leaky(g_as[w] + ad_d);

    float mx = a_self;
    for (int idx = beg + lane; idx < end; idx += 32) {
        int s = g_csr_src[idx];
        mx = fmaxf(mx, leaky(g_as[s] + ad_d));
    }
    for (int o = 16; o; o >>= 1)
        mx = fmaxf(mx, __shfl_xor_sync(0xffffffffu, mx, o));

    float wself = expf(a_self - mx);
    float denp = 0.f;
    float acc[8];
    if (half == 0) {
        uint4 qa = *(const uint4*)(g_Ah + (size_t)w * HD + hl * 8);
        #pragma unroll
        for (int i = 0; i < 8; i++) acc[i] = 0.f;
        fma8(acc, qa, wself);
    } else {
        #pragma unroll
        for (int i = 0; i < 8; i++) acc[i] = 0.f;
    }

    for (int j0 = beg; j0 < end; j0 += 32) {
        int idx = j0 + lane;
        int s = 0;
        float ww = 0.f;
        if (idx < end) {
            s = g_csr_src[idx];
            ww = expf(leaky(g_as[s] + ad_d) - mx);
            denp += ww;
        }
        int m = min(32, end - j0);
        for (int j = 0; j < m; j += 4) {
            int   sA = __shfl_sync(0xffffffffu, s, j + half);
            float wA = __shfl_sync(0xffffffffu, ww, j + half);
            int   sB = __shfl_sync(0xffffffffu, s, (j + 2 + half) & 31);
            float wB = __shfl_sync(0xffffffffu, ww, (j + 2 + half) & 31);
            if (j + half >= m) wA = 0.f;
            if (j + 2 + half >= m) wB = 0.f;
            uint4 qA = *(const uint4*)(g_Ah + (size_t)sA * HD + hl * 8);
            uint4 qB = *(const uint4*)(g_Ah + (size_t)sB * HD + hl * 8);
            fma8(acc, qA, wA);
            fma8(acc, qB, wB);
        }
    }
    for (int o = 16; o; o >>= 1)
        denp += __shfl_xor_sync(0xffffffffu, denp, o);
    float inv = 1.0f / (denp + wself);

    #pragma unroll
    for (int i = 0; i < 8; i++)
        acc[i] += __shfl_xor_sync(0xffffffffu, acc[i], 16);

    if (half == 0) {
        float o0 = fmaf(acc[0], inv, bg[hl * 8 + 0]);
        float o1 = fmaf(acc[1], inv, bg[hl * 8 + 1]);
        float o2 = fmaf(acc[2], inv, bg[hl * 8 + 2]);
        float o3 = fmaf(acc[3], inv, bg[hl * 8 + 3]);
        float o4 = fmaf(acc[4], inv, bg[hl * 8 + 4]);
        float o5 = fmaf(acc[5], inv, bg[hl * 8 + 5]);
        float o6 = fmaf(acc[6], inv, bg[hl * 8 + 6]);
        float o7 = fmaf(acc[7], inv, bg[hl * 8 + 7]);
        uint4 q;
        q.x = packh2(o0, o1);
        q.y = packh2(o2, o3);
        q.z = packh2(o4, o5);
        q.w = packh2(o6, o7);
        *(uint4*)(g_Bh + (size_t)w * HD + hl * 8) = q;
    }
}

// ================= final: out = relu(Bh) @ Wc + bc (fp16 input) =================
__global__ __launch_bounds__(256) void k_out(const float* __restrict__ Wc,
                                             const float* __restrict__ bc,
                                             float* __restrict__ out, int n) {
    __shared__ float ws[128 * 16];
    for (int i = threadIdx.x; i < 128 * 16 / 4; i += 256)
        ((float4*)ws)[i] = ((const float4*)Wc)[i];
    __syncthreads();
    int i = blockIdx.x * blockDim.x + threadIdx.x;
    if (i >= n) return;

    float o16[16];
    for (int c = 0; c < 16; c++) o16[c] = bc[c];

    const __half* brow = g_Bh + (size_t)i * HD;
    #pragma unroll 4
    for (int k2 = 0; k2 < 64; k2++) {
        __half2 h = *(const __half2*)(brow + k2 * 2);
        float2 f = __half22float2(h);
        float b0 = fmaxf(f.x, 0.f);
        float b1 = fmaxf(f.y, 0.f);
        const float* w0 = ws + (k2 * 2) * 16;
        const float* w1 = w0 + 16;
        #pragma unroll
        for (int c = 0; c < 16; c++)
            o16[c] = fmaf(b0, w0[c], fmaf(b1, w1[c], o16[c]));
    }
    float* op = out + (size_t)i * 16;
    for (int c = 0; c < 16; c++) op[c] = o16[c];
}

static inline int ceildiv(int a, int b) { return (a + b - 1) / b; }

extern "C" void kernel_launch(void* const* d_in, const int* in_sizes, int n_in,
                              void* d_out, int out_size) {
    const float* x       = (const float*)d_in[0];
    const int*   ei      = (const int*)d_in[1];
    const float* ew      = (const float*)d_in[2];
    const float* W1      = (const float*)d_in[3];
    const float* b1      = (const float*)d_in[4];
    const float* W2      = (const float*)d_in[5];
    const float* b2      = (const float*)d_in[6];
    const float* Wg      = (const float*)d_in[7];
    const float* att_src = (const float*)d_in[8];
    const float* att_dst = (const float*)d_in[9];
    const float* bg      = (const float*)d_in[10];
    const float* Wc      = (const float*)d_in[11];
    const float* bc      = (const float*)d_in[12];

    int n = in_sizes[0] / HD;
    int e = in_sizes[2];
    const int* src = ei;
    const int* dst = ei + e;

    __half* dAh = nullptr;
    __half* dBh = nullptr;
    __half* dWh = nullptr;
    cudaGetSymbolAddress((void**)&dAh, g_Ah);
    cudaGetSymbolAddress((void**)&dBh, g_Bh);
    cudaGetSymbolAddress((void**)&dWh, g_Wh);

    const int SMEM = 3 * 128 * LDW * (int)sizeof(__half);   // 104448
    cudaFuncSetAttribute(k_gemm_tc<false>, cudaFuncAttributeMaxDynamicSharedMemorySize, SMEM);
    cudaFuncSetAttribute(k_gemm_tc<true>,  cudaFuncAttributeMaxDynamicSharedMemorySize, SMEM);

    static cudaStream_t sB = nullptr;
    static cudaEvent_t evFork = nullptr, evJoin = nullptr;
    if (!sB) {
        cudaStreamCreateWithFlags(&sB, cudaStreamNonBlocking);
        cudaEventCreateWithFlags(&evFork, cudaEventDisableTiming);
        cudaEventCreateWithFlags(&evJoin, cudaEventDisableTiming);
    }

    const int tb = 256;
    const int tot_tiles = ceildiv(n, 128);
    const int gt = (tot_tiles < 296) ? tot_tiles : 296;
    const int ga = ceildiv(n, 8);
    const int nb = ceildiv(n, SCAN_B);

    // ---- fork: chain B (CSR build) || chain A (prep + gemm1) ----
    cudaEventRecord(evFork, 0);
    cudaStreamWaitEvent(sB, evFork, 0);

    k_zero<<<ceildiv(n, tb), tb, 0, sB>>>(n);
    k_count_deg<<<ceildiv(e, tb), tb, 0, sB>>>(dst, ew, e);
    k_scan1<<<nb, SCAN_B, 0, sB>>>(n);
    k_scan3_dinv<<<ceildiv(n, tb), tb, 0, sB>>>(n, nb);
    k_fill<<<ceildiv(e, tb), tb, 0, sB>>>(src, dst, ew, e);
    cudaEventRecord(evJoin, sB);

    k_prep<<<ceildiv(n * 32, tb), tb>>>(x, W1, W2, Wg, n);
    k_gemm_tc<false><<<gt, 512, SMEM>>>(dBh, dWh, dAh, nullptr, nullptr, n, tot_tiles);

    cudaStreamWaitEvent(0, evJoin, 0);

    k_gcn_agg<<<ga, tb>>>(b1, n);
    k_gemm_tc<false><<<gt, 512, SMEM>>>(dBh, dWh + 16384, dAh, nullptr, nullptr, n, tot_tiles);
    k_gcn_agg<<<ga, tb>>>(b2, n);
    k_gemm_tc<true><<<gt, 512, SMEM>>>(dBh, dWh + 32768, dAh, att_src, att_dst, n, tot_tiles);
    k_gat_agg<<<ga, tb>>>(bg, n);
    k_out<<<ceildiv(n, tb), tb>>>(Wc, bc, (float*)d_out, n);
}